// round 2
// baseline (speedup 1.0000x reference)
#include <cuda_runtime.h>
#include <cstdint>

// Problem constants
#define SLEN 2048
#define BATCH 64
#define HID 512
#define G4 2048           // 4*HID
#define NB_REC 128        // persistent blocks (<= 148 SMs, 1 block/SM)

// Scratch (device globals: no allocation allowed)
static __device__ float g_xp[(size_t)SLEN * G4 * BATCH]; // x_proj, layout [s][g][b], 1 GiB
static __device__ float g_hT[2][HID * BATCH];            // transposed h, layout [j][b], ping-pong
static __device__ unsigned g_count;
static __device__ unsigned g_epoch;

// ---------------- packed f32x2 helpers ----------------
__device__ __forceinline__ uint64_t f2_pack(float x, float y) {
    uint64_t r; uint32_t xu = __float_as_uint(x), yu = __float_as_uint(y);
    asm("mov.b64 %0, {%1, %2};" : "=l"(r) : "r"(xu), "r"(yu));
    return r;
}
__device__ __forceinline__ uint64_t f2_dup(float x) {
    uint64_t r; uint32_t xu = __float_as_uint(x);
    asm("mov.b64 %0, {%1, %1};" : "=l"(r) : "r"(xu));
    return r;
}
__device__ __forceinline__ void f2_fma(uint64_t& d, uint64_t a, uint64_t b) {
    asm("fma.rn.f32x2 %0, %1, %2, %0;" : "+l"(d) : "l"(a), "l"(b));
}
__device__ __forceinline__ float2 f2_unpack(uint64_t v) {
    uint32_t lo, hi;
    asm("mov.b64 {%0, %1}, %2;" : "=r"(lo), "=r"(hi) : "l"(v));
    return make_float2(__uint_as_float(lo), __uint_as_float(hi));
}

// ---------------- kernel 0: transpose h_prev -> g_hT[1] ----------------
__global__ void init_hT_kernel(const float* __restrict__ h_prev) {
    int idx = blockIdx.x * blockDim.x + threadIdx.x;   // 0..32767
    int j = idx >> 6, b = idx & 63;
    g_hT[1][idx] = h_prev[b * HID + j];
}

// ---------------- kernel 1: x_proj GEMM ----------------
// C[m][g] = sum_k A[m][k] * W[g][k] + bias,  m = s*64+b (131072), g in 2048, K=512
// Output layout: g_xp[s][g][b]  (b-contiguous -> coalesced in phase 2)
// Tile: BM=128 (2 s values), BN=128, BK=16. 256 threads, micro-tile 8m x 8g,
// f32x2-packed over the m direction (a-operand = m-pair, b-operand = dup gate weight).
__global__ __launch_bounds__(256, 2) void xproj_gemm_kernel(
    const float* __restrict__ A,    // (131072, 512)
    const float* __restrict__ W,    // (2048, 512)
    const float* __restrict__ bi,
    const float* __restrict__ bh)
{
    __shared__ float Ash[16][132];   // [k][m] transposed, padded
    __shared__ float Bsh[16][132];   // [k][g] transposed, padded

    const int tid = threadIdx.x;
    const int tx = tid & 15;     // g direction (8 g's each)
    const int ty = tid >> 4;     // m direction (8 m's each)
    const int m0 = blockIdx.x * 128;
    const int g0 = blockIdx.y * 128;

    uint64_t acc[8][4];
#pragma unroll
    for (int g = 0; g < 8; ++g)
#pragma unroll
        for (int p = 0; p < 4; ++p) acc[g][p] = 0ull;

    for (int kt = 0; kt < 32; ++kt) {
        const int k0 = kt * 16;
#pragma unroll
        for (int i = 0; i < 2; ++i) {
            int idx = tid + i * 256;           // 0..511 float4 slots
            int r = idx >> 2, c4 = idx & 3;
            float4 va = *(const float4*)(A + (size_t)(m0 + r) * 512 + k0 + c4 * 4);
            Ash[c4 * 4 + 0][r] = va.x; Ash[c4 * 4 + 1][r] = va.y;
            Ash[c4 * 4 + 2][r] = va.z; Ash[c4 * 4 + 3][r] = va.w;
            float4 vb = *(const float4*)(W + (size_t)(g0 + r) * 512 + k0 + c4 * 4);
            Bsh[c4 * 4 + 0][r] = vb.x; Bsh[c4 * 4 + 1][r] = vb.y;
            Bsh[c4 * 4 + 2][r] = vb.z; Bsh[c4 * 4 + 3][r] = vb.w;
        }
        __syncthreads();
#pragma unroll
        for (int kk = 0; kk < 16; ++kk) {
            uint64_t a[4];
            const uint64_t* ap = (const uint64_t*)&Ash[kk][ty * 8];
            a[0] = ap[0]; a[1] = ap[1]; a[2] = ap[2]; a[3] = ap[3];
            float4 q0 = *(const float4*)&Bsh[kk][tx * 8];
            float4 q1 = *(const float4*)&Bsh[kk][tx * 8 + 4];
            float bv[8] = {q0.x, q0.y, q0.z, q0.w, q1.x, q1.y, q1.z, q1.w};
#pragma unroll
            for (int g = 0; g < 8; ++g) {
                uint64_t bd = f2_dup(bv[g]);
                f2_fma(acc[g][0], a[0], bd);
                f2_fma(acc[g][1], a[1], bd);
                f2_fma(acc[g][2], a[2], bd);
                f2_fma(acc[g][3], a[3], bd);
            }
        }
        __syncthreads();
    }

    // epilogue: thread's 8 m's are consecutive within one s -> two 16B stores per g
    const int s  = blockIdx.x * 2 + (ty >> 3);
    const int b0 = (ty & 7) * 8;
#pragma unroll
    for (int g = 0; g < 8; ++g) {
        int gg = g0 + tx * 8 + g;
        float bsum = __ldg(bi + gg) + __ldg(bh + gg);
        float2 p0 = f2_unpack(acc[g][0]);
        float2 p1 = f2_unpack(acc[g][1]);
        float2 p2 = f2_unpack(acc[g][2]);
        float2 p3 = f2_unpack(acc[g][3]);
        float4 v0 = make_float4(p0.x + bsum, p0.y + bsum, p1.x + bsum, p1.y + bsum);
        float4 v1 = make_float4(p2.x + bsum, p2.y + bsum, p3.x + bsum, p3.y + bsum);
        float* dst = g_xp + ((size_t)s * G4 + gg) * 64 + b0;
        *(float4*)dst = v0;
        *(float4*)(dst + 4) = v1;
    }
}

// ---------------- grid barrier (sense/epoch, all blocks co-resident) ----------------
__device__ __forceinline__ void grid_barrier() {
    __syncthreads();
    if (threadIdx.x == 0) {
        __threadfence();
        volatile unsigned* ep = &g_epoch;
        unsigned e = *ep;
        if (atomicAdd(&g_count, 1u) == NB_REC - 1) {
            g_count = 0;
            __threadfence();
            atomicAdd(&g_epoch, 1u);     // release
        } else {
            while (*ep == e) { __nanosleep(32); }
        }
        __threadfence();
    }
    __syncthreads();
}

// ---------------- kernel 2: persistent recurrent LSTM ----------------
// 128 blocks x 256 threads. Block owns 4 hidden units j = blk*4+u.
// Thread = (b, u): computes all 4 gates for (b, j). c lives in a register.
// h ping-pongs through g_hT (transposed [j][b]); staged to SMEM per step via cp.async.cg
// in 8 overlapped chunks. W_hh rows for the block's units resident in SMEM as
// gate-pair float2 arrays -> one LDS.64 per f32x2 FMA.
__global__ __launch_bounds__(256, 1) void lstm_rec_kernel(
    const float* __restrict__ c_prev,
    const float* __restrict__ Whh,
    float* __restrict__ out)
{
    extern __shared__ float sm[];
    float* Wif = sm;               // [u][k] interleaved (w_i, w_f): 4096 floats
    float* Wgo = sm + 4096;        // [u][k] interleaved (w_g, w_o): 4096 floats
    float* hsh = sm + 8192;        // [k][b] : 512*64 floats (128 KB)

    const int tid = threadIdx.x;
    const int b = tid & 63;
    const int u = tid >> 6;
    const int j = blockIdx.x * 4 + u;

    // load W_hh rows for this block's 4 units into SMEM, gate-pair packed
    for (int idx = tid; idx < 4 * 512; idx += 256) {
        int uu = idx >> 9, k = idx & 511;
        int jj = blockIdx.x * 4 + uu;
        Wif[idx * 2 + 0] = Whh[(size_t)(0 * HID + jj) * HID + k];
        Wif[idx * 2 + 1] = Whh[(size_t)(1 * HID + jj) * HID + k];
        Wgo[idx * 2 + 0] = Whh[(size_t)(2 * HID + jj) * HID + k];
        Wgo[idx * 2 + 1] = Whh[(size_t)(3 * HID + jj) * HID + k];
    }

    float c = c_prev[b * HID + j];

    // prefetch x_proj for s=0 (coalesced: b-contiguous)
    float xi = __ldg(g_xp + ((size_t)0 * G4 + 0 * HID + j) * 64 + b);
    float xf = __ldg(g_xp + ((size_t)0 * G4 + 1 * HID + j) * 64 + b);
    float xg = __ldg(g_xp + ((size_t)0 * G4 + 2 * HID + j) * 64 + b);
    float xo = __ldg(g_xp + ((size_t)0 * G4 + 3 * HID + j) * 64 + b);

    uint32_t hsh_s = (uint32_t)__cvta_generic_to_shared(hsh);
    const uint64_t* WifU = (const uint64_t*)Wif;
    const uint64_t* WgoU = (const uint64_t*)Wgo;

    __syncthreads();   // W tiles ready

    for (int s = 0; s < SLEN; ++s) {
        const float* hsrc = g_hT[(s + 1) & 1];

        // stage chunk 0 (4096 floats) via cp.async.cg (L2-coherent after barrier)
#pragma unroll
        for (int i = 0; i < 4; ++i) {
            int f4 = tid + i * 256;
            asm volatile("cp.async.cg.shared.global [%0], [%1], 16;"
                         :: "r"(hsh_s + f4 * 16), "l"(hsrc + f4 * 4));
        }
        asm volatile("cp.async.commit_group;");

        uint64_t acc0 = f2_pack(xi, xf);   // (z_i, z_f)
        uint64_t acc1 = f2_pack(xg, xo);   // (z_g, z_o)

        // prefetch x_proj for s+1 (hidden behind this step's compute)
        if (s < SLEN - 1) {
            size_t nb = (size_t)(s + 1) * G4 * 64;
            xi = __ldg(g_xp + nb + (size_t)(0 * HID + j) * 64 + b);
            xf = __ldg(g_xp + nb + (size_t)(1 * HID + j) * 64 + b);
            xg = __ldg(g_xp + nb + (size_t)(2 * HID + j) * 64 + b);
            xo = __ldg(g_xp + nb + (size_t)(3 * HID + j) * 64 + b);
        }

        for (int ch = 0; ch < 8; ++ch) {
            if (ch < 7) {
                const float* src = hsrc + (ch + 1) * 4096;
                uint32_t dst = hsh_s + (uint32_t)(ch + 1) * 16384u;
#pragma unroll
                for (int i = 0; i < 4; ++i) {
                    int f4 = tid + i * 256;
                    asm volatile("cp.async.cg.shared.global [%0], [%1], 16;"
                                 :: "r"(dst + f4 * 16), "l"(src + f4 * 4));
                }
                asm volatile("cp.async.commit_group;");
                asm volatile("cp.async.wait_group 1;");   // chunk ch landed
            } else {
                asm volatile("cp.async.wait_group 0;");
            }
            __syncthreads();   // other threads' cp.async data visible

            const int kbase = ch * 64;
#pragma unroll 8
            for (int k = 0; k < 64; ++k) {
                float hk = hsh[(kbase + k) * 64 + b];   // conflict-free: lanes = consecutive b
                uint64_t hd = f2_dup(hk);
                f2_fma(acc0, hd, WifU[u * 512 + kbase + k]);  // broadcast LDS.64
                f2_fma(acc1, hd, WgoU[u * 512 + kbase + k]);
            }
        }

        float2 zif = f2_unpack(acc0);
        float2 zgo = f2_unpack(acc1);
        float ig = 1.f / (1.f + __expf(-zif.x));
        float fg = 1.f / (1.f + __expf(-zif.y));
        float gt = tanhf(zgo.x);
        float og = 1.f / (1.f + __expf(-zgo.y));
        c = fg * c + ig * gt;
        float h = og * tanhf(c);

        out[(size_t)s * (BATCH * HID) + b * HID + j] = h;   // output[s][b][j]
        g_hT[s & 1][j * 64 + b] = h;                        // transposed h for next step

        if (s == SLEN - 1) {
            const size_t SBH = (size_t)SLEN * BATCH * HID;  // 67108864
            out[SBH + (size_t)b * HID + j] = h;             // h_f
            out[SBH + (size_t)BATCH * HID + (size_t)b * HID + j] = c;  // c_f
        }

        __threadfence();
        grid_barrier();
    }
}

// ---------------- launch ----------------
extern "C" void kernel_launch(void* const* d_in, const int* in_sizes, int n_in,
                              void* d_out, int out_size) {
    (void)in_sizes; (void)n_in; (void)out_size;
    const float* input  = (const float*)d_in[0];  // (2048, 64, 512)
    const float* h_prev = (const float*)d_in[1];  // (64, 512)
    const float* c_prev = (const float*)d_in[2];  // (64, 512)
    const float* w_ih   = (const float*)d_in[3];  // (2048, 512)
    const float* w_hh   = (const float*)d_in[4];  // (2048, 512)
    const float* b_ih   = (const float*)d_in[5];  // (2048,)
    const float* b_hh   = (const float*)d_in[6];  // (2048,)
    float* out = (float*)d_out;

    cudaFuncSetAttribute(lstm_rec_kernel,
                         cudaFuncAttributeMaxDynamicSharedMemorySize, 163840);

    init_hT_kernel<<<128, 256>>>(h_prev);

    dim3 g1(131072 / 128, 2048 / 128);   // (1024, 16)
    xproj_gemm_kernel<<<g1, 256>>>(input, w_ih, b_ih, b_hh);

    lstm_rec_kernel<<<NB_REC, 256, 163840>>>(c_prev, w_hh, out);
}

// round 3
// speedup vs baseline: 1.4256x; 1.4256x over previous
#include <cuda_runtime.h>
#include <cstdint>

#define SLEN 2048
#define BATCH 64
#define HID 512
#define G4 2048
#define NB_REC 128
#define TPB 256

// ---------------- scratch (device globals) ----------------
static __device__ float g_xp[(size_t)SLEN * G4 * BATCH]; // x_proj [s][g][b], 1 GiB
static __device__ float g_hT[2][HID * BATCH];            // transposed h [j][b], ping-pong
static __device__ unsigned g_count;
static __device__ unsigned g_epoch;

// ---------------- packed f32x2 helpers ----------------
__device__ __forceinline__ uint64_t f2_pack(float x, float y) {
    uint64_t r; uint32_t xu = __float_as_uint(x), yu = __float_as_uint(y);
    asm("mov.b64 %0, {%1, %2};" : "=l"(r) : "r"(xu), "r"(yu));
    return r;
}
__device__ __forceinline__ uint64_t f2_dup(float x) {
    uint64_t r; uint32_t xu = __float_as_uint(x);
    asm("mov.b64 %0, {%1, %1};" : "=l"(r) : "r"(xu));
    return r;
}
__device__ __forceinline__ void f2_fma(uint64_t& d, uint64_t a, uint64_t b) {
    asm("fma.rn.f32x2 %0, %1, %2, %0;" : "+l"(d) : "l"(a), "l"(b));
}
__device__ __forceinline__ void f2_add(uint64_t& d, uint64_t a) {
    asm("add.rn.f32x2 %0, %1, %0;" : "+l"(d) : "l"(a));
}
__device__ __forceinline__ float2 f2_unpack(uint64_t v) {
    uint32_t lo, hi;
    asm("mov.b64 {%0, %1}, %2;" : "=r"(lo), "=r"(hi) : "l"(v));
    return make_float2(__uint_as_float(lo), __uint_as_float(hi));
}

// ---------------- kernel 1: x_proj GEMM (unchanged from R1, FMA-bound) ----------------
__global__ __launch_bounds__(256, 2) void xproj_gemm_kernel(
    const float* __restrict__ A,    // (131072, 512)
    const float* __restrict__ W,    // (2048, 512)
    const float* __restrict__ bi,
    const float* __restrict__ bh)
{
    __shared__ float Ash[16][132];
    __shared__ float Bsh[16][132];

    const int tid = threadIdx.x;
    const int tx = tid & 15;
    const int ty = tid >> 4;
    const int m0 = blockIdx.x * 128;
    const int g0 = blockIdx.y * 128;

    uint64_t acc[8][4];
#pragma unroll
    for (int g = 0; g < 8; ++g)
#pragma unroll
        for (int p = 0; p < 4; ++p) acc[g][p] = 0ull;

    for (int kt = 0; kt < 32; ++kt) {
        const int k0 = kt * 16;
#pragma unroll
        for (int i = 0; i < 2; ++i) {
            int idx = tid + i * 256;
            int r = idx >> 2, c4 = idx & 3;
            float4 va = *(const float4*)(A + (size_t)(m0 + r) * 512 + k0 + c4 * 4);
            Ash[c4 * 4 + 0][r] = va.x; Ash[c4 * 4 + 1][r] = va.y;
            Ash[c4 * 4 + 2][r] = va.z; Ash[c4 * 4 + 3][r] = va.w;
            float4 vb = *(const float4*)(W + (size_t)(g0 + r) * 512 + k0 + c4 * 4);
            Bsh[c4 * 4 + 0][r] = vb.x; Bsh[c4 * 4 + 1][r] = vb.y;
            Bsh[c4 * 4 + 2][r] = vb.z; Bsh[c4 * 4 + 3][r] = vb.w;
        }
        __syncthreads();
#pragma unroll
        for (int kk = 0; kk < 16; ++kk) {
            uint64_t a[4];
            const uint64_t* ap = (const uint64_t*)&Ash[kk][ty * 8];
            a[0] = ap[0]; a[1] = ap[1]; a[2] = ap[2]; a[3] = ap[3];
            float4 q0 = *(const float4*)&Bsh[kk][tx * 8];
            float4 q1 = *(const float4*)&Bsh[kk][tx * 8 + 4];
            float bv[8] = {q0.x, q0.y, q0.z, q0.w, q1.x, q1.y, q1.z, q1.w};
#pragma unroll
            for (int g = 0; g < 8; ++g) {
                uint64_t bd = f2_dup(bv[g]);
                f2_fma(acc[g][0], a[0], bd);
                f2_fma(acc[g][1], a[1], bd);
                f2_fma(acc[g][2], a[2], bd);
                f2_fma(acc[g][3], a[3], bd);
            }
        }
        __syncthreads();
    }

    const int s  = blockIdx.x * 2 + (ty >> 3);
    const int b0 = (ty & 7) * 8;
#pragma unroll
    for (int g = 0; g < 8; ++g) {
        int gg = g0 + tx * 8 + g;
        float bsum = __ldg(bi + gg) + __ldg(bh + gg);
        float2 p0 = f2_unpack(acc[g][0]);
        float2 p1 = f2_unpack(acc[g][1]);
        float2 p2 = f2_unpack(acc[g][2]);
        float2 p3 = f2_unpack(acc[g][3]);
        float4 v0 = make_float4(p0.x + bsum, p0.y + bsum, p1.x + bsum, p1.y + bsum);
        float4 v1 = make_float4(p2.x + bsum, p2.y + bsum, p3.x + bsum, p3.y + bsum);
        float* dst = g_xp + ((size_t)s * G4 + gg) * 64 + b0;
        *(float4*)dst = v0;
        *(float4*)(dst + 4) = v1;
    }
}

// ---------------- grid barrier: acq_rel arrive + acquire spin ----------------
__device__ __forceinline__ void grid_barrier() {
    __syncthreads();
    if (threadIdx.x == 0) {
        unsigned e;
        asm volatile("ld.relaxed.gpu.global.u32 %0, [%1];"
                     : "=r"(e) : "l"(&g_epoch) : "memory");
        unsigned old;
        asm volatile("atom.add.acq_rel.gpu.global.u32 %0, [%1], %2;"
                     : "=r"(old) : "l"(&g_count), "r"(1u) : "memory");
        if (old == NB_REC - 1) {
            asm volatile("st.relaxed.gpu.global.u32 [%0], %1;"
                         :: "l"(&g_count), "r"(0u) : "memory");
            asm volatile("red.add.release.gpu.global.u32 [%0], %1;"
                         :: "l"(&g_epoch), "r"(1u) : "memory");
        } else {
            unsigned cur;
            do {
                asm volatile("ld.acquire.gpu.global.u32 %0, [%1];"
                             : "=r"(cur) : "l"(&g_epoch) : "memory");
            } while (cur == e);
        }
    }
    __syncthreads();
}

// ---------------- kernel 2: persistent recurrent LSTM (crossbar-aware) ----------------
// 128 blocks x 256 threads. Block owns 4 hidden units (16 gate-rows), all 64 b.
// Warp w owns the k-slice [w*64, (w+1)*64): stages its own 16KB of hT via
// warp-local cp.async (no __syncthreads in mainloop), computes partial z.
// Lane = (gate-group gg in {0,1}) x (b-quad bq in 0..15); thread tile = 8 rows x 4 b
// = 16 f32x2 accumulators. W pre-duplicated in SMEM as (w,w) pairs -> LDS.128
// broadcast, zero dup-movs. Per-step k-reduction + activations through SMEM.
__global__ __launch_bounds__(TPB, 1) void lstm_rec_kernel(
    const float* __restrict__ h_prev,
    const float* __restrict__ c_prev,
    const float* __restrict__ Whh,
    float* __restrict__ out)
{
    extern __shared__ char smp[];
    // layout: WD  [512][16] float2 dup            : [0, 64KB)
    //         hsh [512][64] float (per-warp 16KB) : [64KB, 192KB)
    //         ACC[w] aliases hsh + w*16KB, 4KB each (warp's slice, consumed)
    //         zbuf aliases hsh + 4KB (4KB); hbuf aliases hsh + 8KB (1KB)
    uint64_t*       WDu  = (uint64_t*)smp;
    float*          hshf = (float*)(smp + 65536);
    float*          zbf  = (float*)(smp + 65536 + 4096);
    float*          hbuf = (float*)(smp + 65536 + 8192);

    const int tid  = threadIdx.x;
    const int w    = tid >> 5;
    const int lane = tid & 31;
    const int gg   = lane >> 4;     // gate-group 0/1 (rows gg*8 .. gg*8+7)
    const int bq   = lane & 15;     // b-quad
    const int u    = tid >> 6;      // activation mapping: hidden unit 0..3
    const int bb   = tid & 63;      // activation mapping: batch
    const int j    = blockIdx.x * 4 + u;

    // --- setup: W duplicated pairs in SMEM; WD[k][r] = (w,w), r = u*4+g ---
    for (int idx = tid; idx < 512 * 16; idx += TPB) {
        int k = idx >> 4, r = idx & 15;
        int uu = r >> 2, g = r & 3;
        float wv = Whh[((size_t)(g * HID + blockIdx.x * 4 + uu)) * HID + k];
        WDu[idx] = f2_dup(wv);
    }
    // --- fused init: transpose h_prev into g_hT[1] (block's own units) ---
    g_hT[1][j * 64 + bb] = h_prev[(size_t)bb * HID + j];

    float c = c_prev[(size_t)bb * HID + j];

    // prefetch x_proj for s=0 (b-contiguous, coalesced)
    float xi = g_xp[((size_t)0 * G4 + 0 * HID + j) * 64 + bb];
    float xf = g_xp[((size_t)0 * G4 + 1 * HID + j) * 64 + bb];
    float xg = g_xp[((size_t)0 * G4 + 2 * HID + j) * 64 + bb];
    float xo = g_xp[((size_t)0 * G4 + 3 * HID + j) * 64 + bb];

    uint32_t hsh_s = (uint32_t)__cvta_generic_to_shared(hshf);
    const uint32_t wdst = hsh_s + (uint32_t)w * 16384u;

    __syncthreads();     // WD ready
    grid_barrier();      // g_hT[1] visible chip-wide

    for (int s = 0; s < SLEN; ++s) {
        const float* hsrc = g_hT[(s + 1) & 1] + (size_t)w * 64 * 64;  // warp's 16KB slice

        // pre-issue sub-chunks 0,1 (warp-local)
#pragma unroll
        for (int sc = 0; sc < 2; ++sc) {
#pragma unroll
            for (int cc = 0; cc < 8; ++cc) {
                asm volatile("cp.async.cg.shared.global [%0], [%1], 16;"
                             :: "r"(wdst + (uint32_t)(sc * 4096 + cc * 512 + lane * 16)),
                                "l"(hsrc + sc * 1024 + cc * 128 + lane * 4));
            }
            asm volatile("cp.async.commit_group;");
        }

        uint64_t acc[8][2];
#pragma unroll
        for (int r = 0; r < 8; ++r) { acc[r][0] = 0ull; acc[r][1] = 0ull; }

        const float zxi = xi, zxf = xf, zxg = xg, zxo = xo;
        if (s + 1 < SLEN) {   // prefetch next-step xp early
            size_t nb = (size_t)(s + 1) * G4 * 64;
            xi = g_xp[nb + (size_t)(0 * HID + j) * 64 + bb];
            xf = g_xp[nb + (size_t)(1 * HID + j) * 64 + bb];
            xg = g_xp[nb + (size_t)(2 * HID + j) * 64 + bb];
            xo = g_xp[nb + (size_t)(3 * HID + j) * 64 + bb];
        }

#pragma unroll
        for (int sc = 0; sc < 4; ++sc) {
            if (sc < 2) {
                const int nsc = sc + 2;
#pragma unroll
                for (int cc = 0; cc < 8; ++cc) {
                    asm volatile("cp.async.cg.shared.global [%0], [%1], 16;"
                                 :: "r"(wdst + (uint32_t)(nsc * 4096 + cc * 512 + lane * 16)),
                                    "l"(hsrc + nsc * 1024 + cc * 128 + lane * 4));
                }
                asm volatile("cp.async.commit_group;");
            }
            if (sc == 0 || sc == 1)      asm volatile("cp.async.wait_group 2;");
            else if (sc == 2)            asm volatile("cp.async.wait_group 1;");
            else                         asm volatile("cp.async.wait_group 0;");
            __syncwarp();   // each lane waited for its own cps; sync makes all visible

            const int kb = w * 64 + sc * 16;
#pragma unroll
            for (int kk = 0; kk < 16; ++kk) {
                const int k = kb + kk;
                const ulonglong2 hv = *(const ulonglong2*)&hshf[k * 64 + bq * 4];
                const ulonglong2 w01 = *(const ulonglong2*)(WDu + k * 16 + gg * 8);
                const ulonglong2 w23 = *(const ulonglong2*)(WDu + k * 16 + gg * 8 + 2);
                const ulonglong2 w45 = *(const ulonglong2*)(WDu + k * 16 + gg * 8 + 4);
                const ulonglong2 w67 = *(const ulonglong2*)(WDu + k * 16 + gg * 8 + 6);
                f2_fma(acc[0][0], hv.x, w01.x); f2_fma(acc[0][1], hv.y, w01.x);
                f2_fma(acc[1][0], hv.x, w01.y); f2_fma(acc[1][1], hv.y, w01.y);
                f2_fma(acc[2][0], hv.x, w23.x); f2_fma(acc[2][1], hv.y, w23.x);
                f2_fma(acc[3][0], hv.x, w23.y); f2_fma(acc[3][1], hv.y, w23.y);
                f2_fma(acc[4][0], hv.x, w45.x); f2_fma(acc[4][1], hv.y, w45.x);
                f2_fma(acc[5][0], hv.x, w45.y); f2_fma(acc[5][1], hv.y, w45.y);
                f2_fma(acc[6][0], hv.x, w67.x); f2_fma(acc[6][1], hv.y, w67.x);
                f2_fma(acc[7][0], hv.x, w67.y); f2_fma(acc[7][1], hv.y, w67.y);
            }
        }

        // --- store partials to per-warp ACC region (aliases warp's own hsh slice) ---
        {
            ulonglong2* A = (ulonglong2*)((char*)smp + 65536 + w * 16384) + lane * 8;
#pragma unroll
            for (int r = 0; r < 8; ++r)
                A[r] = make_ulonglong2(acc[r][0], acc[r][1]);
        }
        __syncthreads();

        // --- reduce over 8 warps: thread handles 2 totals (one ulonglong2 per warp) ---
        {
            const int L  = tid >> 3;          // source lane 0..31
            const int ip = (tid & 7) * 2;     // acc index pair base (even)
            uint64_t t0 = 0ull, t1 = 0ull;
#pragma unroll
            for (int ww = 0; ww < 8; ++ww) {
                ulonglong2 v = *(const ulonglong2*)((char*)smp + 65536 + ww * 16384
                                                    + ((size_t)L * 16 + ip) * 8);
                f2_add(t0, v.x);
                f2_add(t1, v.y);
            }
            const int row  = (L >> 4) * 8 + (ip >> 1);  // gate-row 0..15
            const int bcol = (L & 15) * 4;              // b-quad base
            *(ulonglong2*)&zbf[row * 64 + bcol] = make_ulonglong2(t0, t1);
        }
        __syncthreads();

        // --- activations: thread (u, bb) owns (b=bb, j) across all 4 gates ---
        {
            float z_i = zbf[(u * 4 + 0) * 64 + bb] + zxi;
            float z_f = zbf[(u * 4 + 1) * 64 + bb] + zxf;
            float z_g = zbf[(u * 4 + 2) * 64 + bb] + zxg;
            float z_o = zbf[(u * 4 + 3) * 64 + bb] + zxo;
            float ig = 1.f / (1.f + __expf(-z_i));
            float fg = 1.f / (1.f + __expf(-z_f));
            float gt = tanhf(z_g);
            float og = 1.f / (1.f + __expf(-z_o));
            c = fg * c + ig * gt;
            float h = og * tanhf(c);

            g_hT[s & 1][j * 64 + bb] = h;   // coalesced (lanes = consecutive b)
            hbuf[bb * 4 + u] = h;

            if (s == SLEN - 1) {
                const size_t SBH = (size_t)SLEN * BATCH * HID;
                out[SBH + (size_t)bb * HID + j] = h;                          // h_f
                out[SBH + (size_t)BATCH * HID + (size_t)bb * HID + j] = c;    // c_f
            }
        }
        __syncthreads();
        if (tid < 64) {   // 16B store per batch row
            float4 hv4 = *(const float4*)&hbuf[tid * 4];
            *(float4*)&out[(size_t)s * (BATCH * HID) + (size_t)tid * HID + blockIdx.x * 4] = hv4;
        }

        grid_barrier();
    }
}

// ---------------- launch ----------------
extern "C" void kernel_launch(void* const* d_in, const int* in_sizes, int n_in,
                              void* d_out, int out_size) {
    (void)in_sizes; (void)n_in; (void)out_size;
    const float* input  = (const float*)d_in[0];  // (2048, 64, 512)
    const float* h_prev = (const float*)d_in[1];  // (64, 512)
    const float* c_prev = (const float*)d_in[2];  // (64, 512)
    const float* w_ih   = (const float*)d_in[3];  // (2048, 512)
    const float* w_hh   = (const float*)d_in[4];  // (2048, 512)
    const float* b_ih   = (const float*)d_in[5];  // (2048,)
    const float* b_hh   = (const float*)d_in[6];  // (2048,)
    float* out = (float*)d_out;

    cudaFuncSetAttribute(lstm_rec_kernel,
                         cudaFuncAttributeMaxDynamicSharedMemorySize, 196608);

    dim3 g1(131072 / 128, 2048 / 128);   // (1024, 16)
    xproj_gemm_kernel<<<g1, 256>>>(input, w_ih, b_ih, b_hh);

    lstm_rec_kernel<<<NB_REC, TPB, 196608>>>(h_prev, c_prev, w_hh, out);
}